// round 7
// baseline (speedup 1.0000x reference)
#include <cuda_runtime.h>
#include <cstdint>

// VisibilityHeatmap: out[b,k] = in_bounds(coords[b,k]) && heatmaps[b,k,v,u] > 0.4
// coords: [B,K,2] int32 in (u,v) order; heatmaps: [B,K,H,W] f32.
// Output: [B,K] boolean mask as float32 (0.0f / 1.0f).
//
// 4 outputs/thread, 8 blocks x 256 threads = 2048 threads. Fewest blocks tried
// (minimizes distribution/ramp cost, which the R2-R5 sweep showed is the only
// remaining variable); MLP=4 independent gathers per thread hides latency.
#define B_DIM 128
#define K_DIM 64
#define H_DIM 128
#define W_DIM 128
#define PLANE (H_DIM * W_DIM)     // 16384
#define THRESH 0.4f

__global__ __launch_bounds__(256)
void visibility_kernel(const int4* __restrict__ coords4,
                       const float* __restrict__ heatmaps,
                       float4* __restrict__ out4)
{
    unsigned t = blockIdx.x * 256u + threadIdx.x;   // 0..2047, outputs [4t, 4t+4)

    int4 c01 = coords4[2u * t];       // (u0,v0,u1,v1)
    int4 c23 = coords4[2u * t + 1u];  // (u2,v2,u3,v3)

    int u0 = c01.x, v0 = c01.y, u1 = c01.z, v1 = c01.w;
    int u2 = c23.x, v2 = c23.y, u3 = c23.z, v3 = c23.w;

    bool ib0 = (v0 > -1) & (u0 > -1) & (v0 < H_DIM) & (u0 < W_DIM);
    bool ib1 = (v1 > -1) & (u1 > -1) & (v1 < H_DIM) & (u1 < W_DIM);
    bool ib2 = (v2 > -1) & (u2 > -1) & (v2 < H_DIM) & (u2 < W_DIM);
    bool ib3 = (v3 > -1) & (u3 > -1) & (v3 < H_DIM) & (u3 < W_DIM);

    unsigned base = 4u * t * PLANE;   // element offset, max 2^27 — fits u32
    unsigned o0 = base
                + (unsigned)(min(max(v0, 0), H_DIM - 1) * W_DIM + min(max(u0, 0), W_DIM - 1));
    unsigned o1 = base + PLANE
                + (unsigned)(min(max(v1, 0), H_DIM - 1) * W_DIM + min(max(u1, 0), W_DIM - 1));
    unsigned o2 = base + 2u * PLANE
                + (unsigned)(min(max(v2, 0), H_DIM - 1) * W_DIM + min(max(u2, 0), W_DIM - 1));
    unsigned o3 = base + 3u * PLANE
                + (unsigned)(min(max(v3, 0), H_DIM - 1) * W_DIM + min(max(u3, 0), W_DIM - 1));

    // 4 independent gathers — front-batched, latency overlapped (MLP=4)
    float f0 = __ldg(heatmaps + o0);
    float f1 = __ldg(heatmaps + o1);
    float f2 = __ldg(heatmaps + o2);
    float f3 = __ldg(heatmaps + o3);

    float4 r;
    r.x = (ib0 && (f0 > THRESH)) ? 1.0f : 0.0f;
    r.y = (ib1 && (f1 > THRESH)) ? 1.0f : 0.0f;
    r.z = (ib2 && (f2 > THRESH)) ? 1.0f : 0.0f;
    r.w = (ib3 && (f3 > THRESH)) ? 1.0f : 0.0f;
    out4[t] = r;
}

extern "C" void kernel_launch(void* const* d_in, const int* in_sizes, int n_in,
                              void* d_out, int out_size)
{
    const int4*  coords4  = (const int4*)d_in[0];    // [B,K,2] int32, 2 pairs per int4
    const float* heatmaps = (const float*)d_in[1];   // [B,K,H,W] f32
    float4*      out4     = (float4*)d_out;          // [B,K] mask as f32

    // 8192 outputs / 4 per thread = 2048 threads = 8 blocks x 256
    visibility_kernel<<<8, 256>>>(coords4, heatmaps, out4);
}

// round 8
// speedup vs baseline: 1.0047x; 1.0047x over previous
#include <cuda_runtime.h>
#include <cstdint>

// VisibilityHeatmap: out[b,k] = in_bounds(coords[b,k]) && heatmaps[b,k,v,u] > 0.4
// coords: [B,K,2] int32 in (u,v) order; heatmaps: [B,K,H,W] f32.
// Output: [B,K] boolean mask as float32 (0.0f / 1.0f).
//
// Empirically-optimal config from the R2-R6 sweep: 16 blocks x 128 threads,
// 4 outputs/thread (MLP=4 independent gathers). 8 blocks is worse (per-SM
// gather-queue concentration), 32+ blocks is worse (distribution cost).
// 32-bit offset arithmetic (max element offset 2^27) avoids IMAD.WIDE chains.
#define B_DIM 128
#define K_DIM 64
#define H_DIM 128
#define W_DIM 128
#define PLANE (H_DIM * W_DIM)     // 16384
#define THRESH 0.4f

__global__ __launch_bounds__(128)
void visibility_kernel(const int4* __restrict__ coords4,
                       const float* __restrict__ heatmaps,
                       float4* __restrict__ out4)
{
    unsigned t = blockIdx.x * 128u + threadIdx.x;   // 0..2047, outputs [4t, 4t+4)

    int4 c01 = coords4[2u * t];       // (u0,v0,u1,v1)
    int4 c23 = coords4[2u * t + 1u];  // (u2,v2,u3,v3)

    int u0 = c01.x, v0 = c01.y, u1 = c01.z, v1 = c01.w;
    int u2 = c23.x, v2 = c23.y, u3 = c23.z, v3 = c23.w;

    bool ib0 = (v0 > -1) & (u0 > -1) & (v0 < H_DIM) & (u0 < W_DIM);
    bool ib1 = (v1 > -1) & (u1 > -1) & (v1 < H_DIM) & (u1 < W_DIM);
    bool ib2 = (v2 > -1) & (u2 > -1) & (v2 < H_DIM) & (u2 < W_DIM);
    bool ib3 = (v3 > -1) & (u3 > -1) & (v3 < H_DIM) & (u3 < W_DIM);

    unsigned base = 4u * t * PLANE;   // element offset, max 2^27 — fits u32
    unsigned o0 = base
                + (unsigned)(min(max(v0, 0), H_DIM - 1) * W_DIM + min(max(u0, 0), W_DIM - 1));
    unsigned o1 = base + PLANE
                + (unsigned)(min(max(v1, 0), H_DIM - 1) * W_DIM + min(max(u1, 0), W_DIM - 1));
    unsigned o2 = base + 2u * PLANE
                + (unsigned)(min(max(v2, 0), H_DIM - 1) * W_DIM + min(max(u2, 0), W_DIM - 1));
    unsigned o3 = base + 3u * PLANE
                + (unsigned)(min(max(v3, 0), H_DIM - 1) * W_DIM + min(max(u3, 0), W_DIM - 1));

    // 4 independent gathers — front-batched by ptxas, latency overlapped (MLP=4)
    float f0 = __ldg(heatmaps + o0);
    float f1 = __ldg(heatmaps + o1);
    float f2 = __ldg(heatmaps + o2);
    float f3 = __ldg(heatmaps + o3);

    float4 r;
    r.x = (ib0 && (f0 > THRESH)) ? 1.0f : 0.0f;
    r.y = (ib1 && (f1 > THRESH)) ? 1.0f : 0.0f;
    r.z = (ib2 && (f2 > THRESH)) ? 1.0f : 0.0f;
    r.w = (ib3 && (f3 > THRESH)) ? 1.0f : 0.0f;
    out4[t] = r;
}

extern "C" void kernel_launch(void* const* d_in, const int* in_sizes, int n_in,
                              void* d_out, int out_size)
{
    const int4*  coords4  = (const int4*)d_in[0];    // [B,K,2] int32, 2 pairs per int4
    const float* heatmaps = (const float*)d_in[1];   // [B,K,H,W] f32
    float4*      out4     = (float4*)d_out;          // [B,K] mask as f32

    // 8192 outputs / 4 per thread = 2048 threads = 16 blocks x 128
    visibility_kernel<<<16, 128>>>(coords4, heatmaps, out4);
}